// round 1
// baseline (speedup 1.0000x reference)
#include <cuda_runtime.h>
#include <math.h>

#define BB 64
#define TT 1024
#define DD 256
#define HH 128
#define G4 512           // 4*H gate width
#define NTAGS 3
#define M_TOTAL (BB*TT)  // 65536

// ---------------- static scratch (no allocs allowed) ----------------
__device__ float g_gx[(size_t)2 * BB * TT * G4];      // [dir][b][t][512]  268MB
__device__ float g_seq0[(size_t)BB * TT * 2 * HH];    // layer0 output [b][t][256]
__device__ float g_seq1[(size_t)BB * TT * 2 * HH];    // layer1 output
__device__ float g_part[BB];                          // per-batch CRF partial

__device__ __forceinline__ float sigf(float x) { return 1.0f / (1.0f + expf(-x)); }

// =====================================================================
// GEMM: gx[dir][m][n] = sum_k A[m][k] * W_dir[n][k] + b_ih[n] + b_hh[n]
// A: [65536, 256] row-major.  W: [512, 256] row-major.
// Block tile 128x128, BK=16, 256 threads, 8x8 per thread.
// grid: (4 nblk, 512 mblk, 2 dir)
// =====================================================================
__global__ __launch_bounds__(256, 2)
void gemm_gx_kernel(const float* __restrict__ A,
                    const float* __restrict__ Wf, const float* __restrict__ Wb,
                    const float* __restrict__ bihf, const float* __restrict__ bhhf,
                    const float* __restrict__ bihb, const float* __restrict__ bhhb,
                    float* __restrict__ gx)
{
    const int nblk = blockIdx.x;
    const int mblk = blockIdx.y;
    const int dir  = blockIdx.z;
    const float* W   = dir ? Wb   : Wf;
    const float* bih = dir ? bihb : bihf;
    const float* bhh = dir ? bhhb : bhhf;

    __shared__ float As[16][128 + 4];
    __shared__ float Bs[16][128 + 4];

    const int tid = threadIdx.x;
    const int tx = tid & 15;    // 0..15 -> n
    const int ty = tid >> 4;    // 0..15 -> m

    float acc[8][8];
#pragma unroll
    for (int i = 0; i < 8; i++)
#pragma unroll
        for (int j = 0; j < 8; j++) acc[i][j] = 0.0f;

    const int m0 = mblk * 128;
    const int n0 = nblk * 128;

    for (int kc = 0; kc < 256; kc += 16) {
#pragma unroll
        for (int i = 0; i < 2; i++) {
            int id = tid + i * 256;          // 0..511
            int r  = id >> 2;                // 0..127
            int c  = (id & 3) * 4;           // 0,4,8,12
            float4 va = *(const float4*)(A + (size_t)(m0 + r) * 256 + kc + c);
            As[c + 0][r] = va.x; As[c + 1][r] = va.y;
            As[c + 2][r] = va.z; As[c + 3][r] = va.w;
            float4 vb = *(const float4*)(W + (size_t)(n0 + r) * 256 + kc + c);
            Bs[c + 0][r] = vb.x; Bs[c + 1][r] = vb.y;
            Bs[c + 2][r] = vb.z; Bs[c + 3][r] = vb.w;
        }
        __syncthreads();

#pragma unroll
        for (int k = 0; k < 16; k++) {
            float a[8], b[8];
            float4 a0 = *(const float4*)&As[k][ty * 8];
            float4 a1 = *(const float4*)&As[k][ty * 8 + 4];
            float4 b0 = *(const float4*)&Bs[k][tx * 8];
            float4 b1 = *(const float4*)&Bs[k][tx * 8 + 4];
            a[0]=a0.x; a[1]=a0.y; a[2]=a0.z; a[3]=a0.w;
            a[4]=a1.x; a[5]=a1.y; a[6]=a1.z; a[7]=a1.w;
            b[0]=b0.x; b[1]=b0.y; b[2]=b0.z; b[3]=b0.w;
            b[4]=b1.x; b[5]=b1.y; b[6]=b1.z; b[7]=b1.w;
#pragma unroll
            for (int i = 0; i < 8; i++)
#pragma unroll
                for (int j = 0; j < 8; j++)
                    acc[i][j] += a[i] * b[j];
        }
        __syncthreads();
    }

    float* gxd = gx + (size_t)dir * M_TOTAL * G4;
#pragma unroll
    for (int i = 0; i < 8; i++) {
        size_t row = (size_t)(m0 + ty * 8 + i) * G4;
#pragma unroll
        for (int j = 0; j < 8; j++) {
            int n = n0 + tx * 8 + j;
            gxd[row + n] = acc[i][j] + bih[n] + bhh[n];
        }
    }
}

// =====================================================================
// LSTM scan: one block per (dir, batch). 512 threads, thread j owns gate
// row j. W_hh split: 80 K-columns in registers, 48 K-columns in smem.
// h/c live in smem/regs -> no cross-block traffic, no grid sync.
// =====================================================================
#define KREG 80
#define KS   48
#define SCAN_SMEM ((KS/4)*512*16 + (HH + G4)*4)   // 98304 + 2560 = 100864

__global__ __launch_bounds__(512, 1)
void lstm_scan_kernel(const float* __restrict__ gx,
                      const float* __restrict__ w_hh_f,
                      const float* __restrict__ w_hh_b,
                      float* __restrict__ outseq)
{
    const int bid = blockIdx.x;     // 0..127
    const int dir = bid >> 6;
    const int b   = bid & 63;
    const int j   = threadIdx.x;    // 0..511
    const float* W = dir ? w_hh_b : w_hh_f;

    extern __shared__ float smem[];
    float4* ws4 = (float4*)smem;                    // [KS/4][512]
    float*  sh  = smem + (KS / 4) * 512 * 4;        // h[128]
    float*  sg  = sh + HH;                          // gates[512]

    // load weights: regs for k < KREG
    float wr[KREG];
#pragma unroll
    for (int k = 0; k < KREG; k++) wr[k] = W[(size_t)j * HH + k];
    // smem (transposed, float4 over k) for k in [KREG, 128)
#pragma unroll
    for (int k4 = 0; k4 < KS / 4; k4++) {
        const float* wp = W + (size_t)j * HH + KREG + k4 * 4;
        ws4[k4 * 512 + j] = make_float4(wp[0], wp[1], wp[2], wp[3]);
    }
    if (j < HH) sh[j] = 0.0f;
    float c = 0.0f;
    __syncthreads();

    const float* gxb = gx + ((size_t)dir * BB + b) * TT * G4;
    const int dt = dir ? -1 : 1;
    int tt = dir ? (TT - 1) : 0;
    float gcur = gxb[(size_t)tt * G4 + j];

    for (int t = 0; t < TT; t++) {
        int ttn = tt + dt;
        float gnext = (t < TT - 1) ? gxb[(size_t)ttn * G4 + j] : 0.0f;

        float acc = gcur;
#pragma unroll
        for (int k = 0; k < KREG; k += 4) {
            float4 h4 = *(const float4*)(sh + k);
            acc += wr[k] * h4.x + wr[k + 1] * h4.y + wr[k + 2] * h4.z + wr[k + 3] * h4.w;
        }
#pragma unroll
        for (int k4 = 0; k4 < KS / 4; k4++) {
            float4 w4 = ws4[k4 * 512 + j];
            float4 h4 = *(const float4*)(sh + KREG + k4 * 4);
            acc += w4.x * h4.x + w4.y * h4.y + w4.z * h4.z + w4.w * h4.w;
        }
        sg[j] = acc;
        __syncthreads();

        if (j < HH) {
            float ig = sigf(sg[j]);
            float fg = sigf(sg[j + 128]);
            float gg = tanhf(sg[j + 256]);
            float og = sigf(sg[j + 384]);
            c = fg * c + ig * gg;
            float h = og * tanhf(c);
            sh[j] = h;
            outseq[((size_t)b * TT + tt) * (2 * HH) + dir * HH + j] = h;
        }
        __syncthreads();

        gcur = gnext;
        tt = ttn;
    }
}

// =====================================================================
// Emissions: em[r][tag] = seq1[r][:] . fc_w[tag][:] + fc_b[tag]
// one warp per row r.
// =====================================================================
__global__ void emissions_kernel(const float* __restrict__ seq,
                                 const float* __restrict__ fcw,
                                 const float* __restrict__ fcb,
                                 float* __restrict__ em)
{
    int gw = (int)((blockIdx.x * blockDim.x + threadIdx.x) >> 5);
    int lane = threadIdx.x & 31;
    if (gw >= M_TOTAL) return;
    const float* row = seq + (size_t)gw * 256 + lane * 8;
    float4 xa = *(const float4*)(row);
    float4 xb = *(const float4*)(row + 4);
#pragma unroll
    for (int tag = 0; tag < NTAGS; tag++) {
        const float* w = fcw + tag * 256 + lane * 8;
        float4 wa = *(const float4*)(w);
        float4 wb = *(const float4*)(w + 4);
        float p = xa.x * wa.x + xa.y * wa.y + xa.z * wa.z + xa.w * wa.w
                + xb.x * wb.x + xb.y * wb.y + xb.z * wb.z + xb.w * wb.w;
#pragma unroll
        for (int off = 16; off > 0; off >>= 1)
            p += __shfl_xor_sync(0xffffffffu, p, off);
        if (lane == 0) em[(size_t)gw * NTAGS + tag] = p + fcb[tag];
    }
}

// =====================================================================
// CRF: per-batch (numerator - logZ). One warp per batch element.
// =====================================================================
__global__ void crf_batch_kernel(const float* __restrict__ em,   // [64][1024][3]
                                 const int* __restrict__ tags,   // [64][1024]
                                 const float* __restrict__ startv,
                                 const float* __restrict__ endv,
                                 const float* __restrict__ trans, // [3][3]
                                 float* __restrict__ part)
{
    int b = blockIdx.x;
    int lane = threadIdx.x;
    const float* emb = em + (size_t)b * TT * NTAGS;
    const int* tg = tags + (size_t)b * TT;

    // gold-path score pieces (emission + transition sums)
    float s = 0.0f;
    for (int t = lane; t < TT; t += 32) {
        int tag = tg[t];
        s += emb[t * NTAGS + tag];
        if (t > 0) s += trans[tg[t - 1] * NTAGS + tag];
    }
#pragma unroll
    for (int off = 16; off > 0; off >>= 1)
        s += __shfl_xor_sync(0xffffffffu, s, off);

    // forward algorithm: lanes 0..2 hold alpha
    float alpha = -1e30f;
    float tr0 = 0.f, tr1 = 0.f, tr2 = 0.f;
    if (lane < NTAGS) {
        alpha = startv[lane] + emb[lane];
        tr0 = trans[0 * NTAGS + lane];
        tr1 = trans[1 * NTAGS + lane];
        tr2 = trans[2 * NTAGS + lane];
    }
    for (int t = 1; t < TT; t++) {
        float a0 = __shfl_sync(0xffffffffu, alpha, 0);
        float a1 = __shfl_sync(0xffffffffu, alpha, 1);
        float a2 = __shfl_sync(0xffffffffu, alpha, 2);
        if (lane < NTAGS) {
            float v0 = a0 + tr0, v1 = a1 + tr1, v2 = a2 + tr2;
            float m = fmaxf(v0, fmaxf(v1, v2));
            alpha = emb[t * NTAGS + lane] + m +
                    logf(expf(v0 - m) + expf(v1 - m) + expf(v2 - m));
        }
    }
    if (lane < NTAGS) alpha += endv[lane];
    float a0 = __shfl_sync(0xffffffffu, alpha, 0);
    float a1 = __shfl_sync(0xffffffffu, alpha, 1);
    float a2 = __shfl_sync(0xffffffffu, alpha, 2);
    if (lane == 0) {
        float m = fmaxf(a0, fmaxf(a1, a2));
        float logZ = m + logf(expf(a0 - m) + expf(a1 - m) + expf(a2 - m));
        float num = s + startv[tg[0]] + endv[tg[TT - 1]];
        part[b] = num - logZ;
    }
}

__global__ void crf_reduce_kernel(const float* __restrict__ part, float* __restrict__ out)
{
    float s = 0.0f;
    for (int i = 0; i < BB; i++) s += part[i];
    out[0] = -s / (float)BB;
}

// =====================================================================
extern "C" void kernel_launch(void* const* d_in, const int* in_sizes, int n_in,
                              void* d_out, int out_size)
{
    const float* x         = (const float*)d_in[0];
    const int*   tags      = (const int*)  d_in[1];
    const float* w_ih_l0   = (const float*)d_in[2];
    const float* w_hh_l0   = (const float*)d_in[3];
    const float* b_ih_l0   = (const float*)d_in[4];
    const float* b_hh_l0   = (const float*)d_in[5];
    const float* w_ih_l0r  = (const float*)d_in[6];
    const float* w_hh_l0r  = (const float*)d_in[7];
    const float* b_ih_l0r  = (const float*)d_in[8];
    const float* b_hh_l0r  = (const float*)d_in[9];
    const float* w_ih_l1   = (const float*)d_in[10];
    const float* w_hh_l1   = (const float*)d_in[11];
    const float* b_ih_l1   = (const float*)d_in[12];
    const float* b_hh_l1   = (const float*)d_in[13];
    const float* w_ih_l1r  = (const float*)d_in[14];
    const float* w_hh_l1r  = (const float*)d_in[15];
    const float* b_ih_l1r  = (const float*)d_in[16];
    const float* b_hh_l1r  = (const float*)d_in[17];
    const float* fc_w      = (const float*)d_in[18];
    const float* fc_b      = (const float*)d_in[19];
    const float* crf_start = (const float*)d_in[20];
    const float* crf_end   = (const float*)d_in[21];
    const float* crf_trans = (const float*)d_in[22];

    float* out = (float*)d_out;

    float *gx, *seq0, *seq1, *part;
    cudaGetSymbolAddress((void**)&gx,   g_gx);
    cudaGetSymbolAddress((void**)&seq0, g_seq0);
    cudaGetSymbolAddress((void**)&seq1, g_seq1);
    cudaGetSymbolAddress((void**)&part, g_part);

    cudaFuncSetAttribute(lstm_scan_kernel,
                         cudaFuncAttributeMaxDynamicSharedMemorySize, SCAN_SMEM);

    dim3 ggrid(4, 512, 2);

    // layer 0
    gemm_gx_kernel<<<ggrid, 256>>>(x, w_ih_l0, w_ih_l0r,
                                   b_ih_l0, b_hh_l0, b_ih_l0r, b_hh_l0r, gx);
    lstm_scan_kernel<<<128, 512, SCAN_SMEM>>>(gx, w_hh_l0, w_hh_l0r, seq0);

    // layer 1
    gemm_gx_kernel<<<ggrid, 256>>>(seq0, w_ih_l1, w_ih_l1r,
                                   b_ih_l1, b_hh_l1, b_ih_l1r, b_hh_l1r, gx);
    lstm_scan_kernel<<<128, 512, SCAN_SMEM>>>(gx, w_hh_l1, w_hh_l1r, seq1);

    // emissions -> d_out[1..]
    emissions_kernel<<<(M_TOTAL * 32 + 255) / 256, 256>>>(seq1, fc_w, fc_b, out + 1);

    // CRF loss -> d_out[0]
    crf_batch_kernel<<<BB, 32>>>(out + 1, tags, crf_start, crf_end, crf_trans, part);
    crf_reduce_kernel<<<1, 1>>>(part, out);
}

// round 2
// speedup vs baseline: 1.0974x; 1.0974x over previous
#include <cuda_runtime.h>
#include <math.h>

#define BB 64
#define TT 1024
#define DD 256
#define HH 128
#define G4 512           // 4*H gate width
#define NTAGS 3
#define M_TOTAL (BB*TT)  // 65536

typedef unsigned long long u64;

// ---------------- static scratch (no allocs allowed) ----------------
__device__ float g_gx[(size_t)2 * BB * TT * G4];      // [dir][b][t][512]
__device__ float g_seq0[(size_t)BB * TT * 2 * HH];    // layer0 output [b][t][256]
__device__ float g_seq1[(size_t)BB * TT * 2 * HH];    // layer1 output
__device__ float g_part[BB];                          // per-batch CRF partial

__device__ __forceinline__ float sigf(float x) { return 1.0f / (1.0f + expf(-x)); }

// ---- packed f32x2 helpers (sm_100+) ----
__device__ __forceinline__ u64 dup2(float x) {
    u64 r; asm("mov.b64 %0, {%1, %1};" : "=l"(r) : "f"(x)); return r;
}
__device__ __forceinline__ void fma2(u64& d, u64 a, u64 b) {
    asm("fma.rn.f32x2 %0, %1, %2, %0;" : "+l"(d) : "l"(a), "l"(b));
}
__device__ __forceinline__ void add2(u64& d, u64 a, u64 b) {
    asm("add.rn.f32x2 %0, %1, %2;" : "=l"(d) : "l"(a), "l"(b));
}
__device__ __forceinline__ float2 unpk(u64 v) {
    float2 f; asm("mov.b64 {%0, %1}, %2;" : "=f"(f.x), "=f"(f.y) : "l"(v)); return f;
}

// =====================================================================
// GEMM: gx[dir][m][n] = sum_k A[m][k] * W_dir[n][k] + b_ih[n] + b_hh[n]
// A: [65536, 256] row-major.  W: [512, 256] row-major.
// Block tile 128x128, BK=16, 256 threads, 8x8 per thread, f32x2 packed.
// grid: (4 nblk, 512 mblk, 2 dir)
// =====================================================================
__global__ __launch_bounds__(256, 2)
void gemm_gx_kernel(const float* __restrict__ A,
                    const float* __restrict__ Wf, const float* __restrict__ Wb,
                    const float* __restrict__ bihf, const float* __restrict__ bhhf,
                    const float* __restrict__ bihb, const float* __restrict__ bhhb,
                    float* __restrict__ gx)
{
    const int nblk = blockIdx.x;
    const int mblk = blockIdx.y;
    const int dir  = blockIdx.z;
    const float* W   = dir ? Wb   : Wf;
    const float* bih = dir ? bihb : bihf;
    const float* bhh = dir ? bhhb : bhhf;

    __shared__ float As[16][128 + 4];
    __shared__ float Bs[16][128 + 4];

    const int tid = threadIdx.x;
    const int tx = tid & 15;    // 0..15 -> n
    const int ty = tid >> 4;    // 0..15 -> m

    u64 acc2[8][4];             // 8 m-rows x 4 n-pairs (fp32 pairs)
#pragma unroll
    for (int i = 0; i < 8; i++)
#pragma unroll
        for (int j = 0; j < 4; j++) acc2[i][j] = 0ull;

    const int m0 = mblk * 128;
    const int n0 = nblk * 128;

    for (int kc = 0; kc < 256; kc += 16) {
#pragma unroll
        for (int i = 0; i < 2; i++) {
            int id = tid + i * 256;          // 0..511
            int r  = id >> 2;                // 0..127
            int c  = (id & 3) * 4;           // 0,4,8,12
            float4 va = *(const float4*)(A + (size_t)(m0 + r) * 256 + kc + c);
            As[c + 0][r] = va.x; As[c + 1][r] = va.y;
            As[c + 2][r] = va.z; As[c + 3][r] = va.w;
            float4 vb = *(const float4*)(W + (size_t)(n0 + r) * 256 + kc + c);
            Bs[c + 0][r] = vb.x; Bs[c + 1][r] = vb.y;
            Bs[c + 2][r] = vb.z; Bs[c + 3][r] = vb.w;
        }
        __syncthreads();

#pragma unroll
        for (int k = 0; k < 16; k++) {
            float4 a0 = *(const float4*)&As[k][ty * 8];
            float4 a1 = *(const float4*)&As[k][ty * 8 + 4];
            u64 ap[8];
            ap[0] = dup2(a0.x); ap[1] = dup2(a0.y);
            ap[2] = dup2(a0.z); ap[3] = dup2(a0.w);
            ap[4] = dup2(a1.x); ap[5] = dup2(a1.y);
            ap[6] = dup2(a1.z); ap[7] = dup2(a1.w);
            const u64* bp = (const u64*)&Bs[k][tx * 8];
            u64 b2[4];
            b2[0] = bp[0]; b2[1] = bp[1]; b2[2] = bp[2]; b2[3] = bp[3];
#pragma unroll
            for (int i = 0; i < 8; i++)
#pragma unroll
                for (int j = 0; j < 4; j++)
                    fma2(acc2[i][j], ap[i], b2[j]);
        }
        __syncthreads();
    }

    float* gxd = gx + (size_t)dir * M_TOTAL * G4;
#pragma unroll
    for (int i = 0; i < 8; i++) {
        size_t row = (size_t)(m0 + ty * 8 + i) * G4;
#pragma unroll
        for (int j = 0; j < 4; j++) {
            int n = n0 + tx * 8 + j * 2;
            float2 v = unpk(acc2[i][j]);
            gxd[row + n]     = v.x + bih[n]     + bhh[n];
            gxd[row + n + 1] = v.y + bih[n + 1] + bhh[n + 1];
        }
    }
}

// =====================================================================
// LSTM scan: one block per (dir, batch). 512 threads, thread j owns gate
// row j. W_hh split: 96 K-columns in registers (48 f32x2 pairs), 32 in
// smem. h/c block-local -> no grid syncs. Dot products via fma.rn.f32x2.
// =====================================================================
#define KREG 96
#define KS   32
#define SCAN_SMEM ((KS/4)*512*16 + (HH + G4)*4)   // 65536 + 2560 = 68096

__global__ __launch_bounds__(512, 1)
void lstm_scan_kernel(const float* __restrict__ gx,
                      const float* __restrict__ w_hh_f,
                      const float* __restrict__ w_hh_b,
                      float* __restrict__ outseq)
{
    const int bid = blockIdx.x;     // 0..127
    const int dir = bid >> 6;
    const int b   = bid & 63;
    const int j   = threadIdx.x;    // 0..511
    const float* W = dir ? w_hh_b : w_hh_f;

    extern __shared__ float smem[];
    ulonglong2* ws2 = (ulonglong2*)smem;            // [KS/4][512] (2 f32x2 pairs each)
    float* sh = smem + (KS / 4) * 512 * 4;          // h[128]
    float* sg = sh + HH;                            // gates[512]

    // register weights: pairs over k, k < KREG
    u64 wr2[KREG / 2];
    {
        const u64* wp = (const u64*)(W + (size_t)j * HH);
#pragma unroll
        for (int p = 0; p < KREG / 2; p++) wr2[p] = wp[p];
    }
    // smem weights for k in [KREG, 128)
#pragma unroll
    for (int k4 = 0; k4 < KS / 4; k4++)
        ws2[k4 * 512 + j] = *(const ulonglong2*)(W + (size_t)j * HH + KREG + k4 * 4);

    if (j < HH) sh[j] = 0.0f;
    float c = 0.0f;
    __syncthreads();

    const float* gxb = gx + ((size_t)dir * BB + b) * TT * G4;
    const int dt = dir ? -1 : 1;
    int tt = dir ? (TT - 1) : 0;
    float gcur = gxb[(size_t)tt * G4 + j];

    for (int t = 0; t < TT; t++) {
        int ttn = tt + dt;
        float gnext = (t < TT - 1) ? gxb[(size_t)ttn * G4 + j] : 0.0f;

        u64 acca = 0ull, accb = 0ull;
#pragma unroll
        for (int p = 0; p < KREG / 2; p += 2) {
            ulonglong2 h2 = *(const ulonglong2*)(sh + p * 2);  // h[2p..2p+3]
            fma2(acca, wr2[p],     h2.x);
            fma2(accb, wr2[p + 1], h2.y);
        }
#pragma unroll
        for (int k4 = 0; k4 < KS / 4; k4++) {
            ulonglong2 w4 = ws2[k4 * 512 + j];
            ulonglong2 h2 = *(const ulonglong2*)(sh + KREG + k4 * 4);
            fma2(acca, w4.x, h2.x);
            fma2(accb, w4.y, h2.y);
        }
        u64 accs; add2(accs, acca, accb);
        float2 av = unpk(accs);
        sg[j] = gcur + av.x + av.y;
        __syncthreads();

        if (j < HH) {
            float ig = sigf(sg[j]);
            float fg = sigf(sg[j + 128]);
            float gg = tanhf(sg[j + 256]);
            float og = sigf(sg[j + 384]);
            c = fg * c + ig * gg;
            float h = og * tanhf(c);
            sh[j] = h;
            outseq[((size_t)b * TT + tt) * (2 * HH) + dir * HH + j] = h;
        }
        __syncthreads();

        gcur = gnext;
        tt = ttn;
    }
}

// =====================================================================
// Emissions: em[r][tag] = seq1[r][:] . fc_w[tag][:] + fc_b[tag]
// one warp per row r.
// =====================================================================
__global__ void emissions_kernel(const float* __restrict__ seq,
                                 const float* __restrict__ fcw,
                                 const float* __restrict__ fcb,
                                 float* __restrict__ em)
{
    int gw = (int)((blockIdx.x * blockDim.x + threadIdx.x) >> 5);
    int lane = threadIdx.x & 31;
    if (gw >= M_TOTAL) return;
    const float* row = seq + (size_t)gw * 256 + lane * 8;
    float4 xa = *(const float4*)(row);
    float4 xb = *(const float4*)(row + 4);
#pragma unroll
    for (int tag = 0; tag < NTAGS; tag++) {
        const float* w = fcw + tag * 256 + lane * 8;
        float4 wa = *(const float4*)(w);
        float4 wb = *(const float4*)(w + 4);
        float p = xa.x * wa.x + xa.y * wa.y + xa.z * wa.z + xa.w * wa.w
                + xb.x * wb.x + xb.y * wb.y + xb.z * wb.z + xb.w * wb.w;
#pragma unroll
        for (int off = 16; off > 0; off >>= 1)
            p += __shfl_xor_sync(0xffffffffu, p, off);
        if (lane == 0) em[(size_t)gw * NTAGS + tag] = p + fcb[tag];
    }
}

// =====================================================================
// CRF: per-batch (numerator - logZ). One warp per batch element.
// =====================================================================
__global__ void crf_batch_kernel(const float* __restrict__ em,   // [64][1024][3]
                                 const int* __restrict__ tags,   // [64][1024]
                                 const float* __restrict__ startv,
                                 const float* __restrict__ endv,
                                 const float* __restrict__ trans, // [3][3]
                                 float* __restrict__ part)
{
    int b = blockIdx.x;
    int lane = threadIdx.x;
    const float* emb = em + (size_t)b * TT * NTAGS;
    const int* tg = tags + (size_t)b * TT;

    float s = 0.0f;
    for (int t = lane; t < TT; t += 32) {
        int tag = tg[t];
        s += emb[t * NTAGS + tag];
        if (t > 0) s += trans[tg[t - 1] * NTAGS + tag];
    }
#pragma unroll
    for (int off = 16; off > 0; off >>= 1)
        s += __shfl_xor_sync(0xffffffffu, s, off);

    float alpha = -1e30f;
    float tr0 = 0.f, tr1 = 0.f, tr2 = 0.f;
    if (lane < NTAGS) {
        alpha = startv[lane] + emb[lane];
        tr0 = trans[0 * NTAGS + lane];
        tr1 = trans[1 * NTAGS + lane];
        tr2 = trans[2 * NTAGS + lane];
    }
    for (int t = 1; t < TT; t++) {
        float a0 = __shfl_sync(0xffffffffu, alpha, 0);
        float a1 = __shfl_sync(0xffffffffu, alpha, 1);
        float a2 = __shfl_sync(0xffffffffu, alpha, 2);
        if (lane < NTAGS) {
            float v0 = a0 + tr0, v1 = a1 + tr1, v2 = a2 + tr2;
            float m = fmaxf(v0, fmaxf(v1, v2));
            alpha = emb[t * NTAGS + lane] + m +
                    logf(expf(v0 - m) + expf(v1 - m) + expf(v2 - m));
        }
    }
    if (lane < NTAGS) alpha += endv[lane];
    float a0 = __shfl_sync(0xffffffffu, alpha, 0);
    float a1 = __shfl_sync(0xffffffffu, alpha, 1);
    float a2 = __shfl_sync(0xffffffffu, alpha, 2);
    if (lane == 0) {
        float m = fmaxf(a0, fmaxf(a1, a2));
        float logZ = m + logf(expf(a0 - m) + expf(a1 - m) + expf(a2 - m));
        float num = s + startv[tg[0]] + endv[tg[TT - 1]];
        part[b] = num - logZ;
    }
}

__global__ void crf_reduce_kernel(const float* __restrict__ part, float* __restrict__ out)
{
    float s = 0.0f;
    for (int i = 0; i < BB; i++) s += part[i];
    out[0] = -s / (float)BB;
}

// =====================================================================
extern "C" void kernel_launch(void* const* d_in, const int* in_sizes, int n_in,
                              void* d_out, int out_size)
{
    const float* x         = (const float*)d_in[0];
    const int*   tags      = (const int*)  d_in[1];
    const float* w_ih_l0   = (const float*)d_in[2];
    const float* w_hh_l0   = (const float*)d_in[3];
    const float* b_ih_l0   = (const float*)d_in[4];
    const float* b_hh_l0   = (const float*)d_in[5];
    const float* w_ih_l0r  = (const float*)d_in[6];
    const float* w_hh_l0r  = (const float*)d_in[7];
    const float* b_ih_l0r  = (const float*)d_in[8];
    const float* b_hh_l0r  = (const float*)d_in[9];
    const float* w_ih_l1   = (const float*)d_in[10];
    const float* w_hh_l1   = (const float*)d_in[11];
    const float* b_ih_l1   = (const float*)d_in[12];
    const float* b_hh_l1   = (const float*)d_in[13];
    const float* w_ih_l1r  = (const float*)d_in[14];
    const float* w_hh_l1r  = (const float*)d_in[15];
    const float* b_ih_l1r  = (const float*)d_in[16];
    const float* b_hh_l1r  = (const float*)d_in[17];
    const float* fc_w      = (const float*)d_in[18];
    const float* fc_b      = (const float*)d_in[19];
    const float* crf_start = (const float*)d_in[20];
    const float* crf_end   = (const float*)d_in[21];
    const float* crf_trans = (const float*)d_in[22];

    float* out = (float*)d_out;

    float *gx, *seq0, *seq1, *part;
    cudaGetSymbolAddress((void**)&gx,   g_gx);
    cudaGetSymbolAddress((void**)&seq0, g_seq0);
    cudaGetSymbolAddress((void**)&seq1, g_seq1);
    cudaGetSymbolAddress((void**)&part, g_part);

    cudaFuncSetAttribute(lstm_scan_kernel,
                         cudaFuncAttributeMaxDynamicSharedMemorySize, SCAN_SMEM);

    dim3 ggrid(4, 512, 2);

    // layer 0
    gemm_gx_kernel<<<ggrid, 256>>>(x, w_ih_l0, w_ih_l0r,
                                   b_ih_l0, b_hh_l0, b_ih_l0r, b_hh_l0r, gx);
    lstm_scan_kernel<<<128, 512, SCAN_SMEM>>>(gx, w_hh_l0, w_hh_l0r, seq0);

    // layer 1
    gemm_gx_kernel<<<ggrid, 256>>>(seq0, w_ih_l1, w_ih_l1r,
                                   b_ih_l1, b_hh_l1, b_ih_l1r, b_hh_l1r, gx);
    lstm_scan_kernel<<<128, 512, SCAN_SMEM>>>(gx, w_hh_l1, w_hh_l1r, seq1);

    // emissions -> d_out[1..]
    emissions_kernel<<<(M_TOTAL * 32 + 255) / 256, 256>>>(seq1, fc_w, fc_b, out + 1);

    // CRF loss -> d_out[0]
    crf_batch_kernel<<<BB, 32>>>(out + 1, tags, crf_start, crf_end, crf_trans, part);
    crf_reduce_kernel<<<1, 1>>>(part, out);
}

// round 5
// speedup vs baseline: 1.7191x; 1.5665x over previous
#include <cuda_runtime.h>
#include <cuda_bf16.h>
#include <math.h>
#include <cstdint>

#define BB 64
#define TT 1024
#define DD 256
#define HH 128
#define G4 512           // 4*H gate width
#define NTAGS 3
#define M_TOTAL (BB*TT)  // 65536

typedef unsigned long long u64;

// single dynamic-shared extern for kernels that need it
extern __shared__ char smem_raw[];

// ---------------- static scratch (no allocs allowed) ----------------
__device__ float g_gx[(size_t)2 * BB * TT * G4];        // [dir][b][t][512]
__device__ float g_seq0[(size_t)BB * TT * 2 * HH];      // layer0 output
__device__ float g_seq1[(size_t)BB * TT * 2 * HH];      // layer1 output
__device__ float g_part[BB];
__device__ __nv_bfloat16 g_xhi[(size_t)M_TOTAL * DD];   // A hi
__device__ __nv_bfloat16 g_xlo[(size_t)M_TOTAL * DD];   // A lo
__device__ __nv_bfloat16 g_whi[(size_t)2 * G4 * DD];    // W hi (2 dirs)
__device__ __nv_bfloat16 g_wlo[(size_t)2 * G4 * DD];    // W lo

__device__ __forceinline__ float sigf(float x) { return 1.0f / (1.0f + expf(-x)); }

// ---- packed f32x2 helpers ----
__device__ __forceinline__ void fma2(u64& d, u64 a, u64 b) {
    asm("fma.rn.f32x2 %0, %1, %2, %0;" : "+l"(d) : "l"(a), "l"(b));
}
__device__ __forceinline__ void add2(u64& d, u64 a, u64 b) {
    asm("add.rn.f32x2 %0, %1, %2;" : "=l"(d) : "l"(a), "l"(b));
}
__device__ __forceinline__ float2 unpk(u64 v) {
    float2 f; asm("mov.b64 {%0, %1}, %2;" : "=f"(f.x), "=f"(f.y) : "l"(v)); return f;
}

__device__ __forceinline__ uint32_t smem_u32(const void* p) {
    uint32_t a;
    asm("{ .reg .u64 t; cvta.to.shared.u64 t, %1; cvt.u32.u64 %0, t; }" : "=r"(a) : "l"(p));
    return a;
}

// ---- ldmatrix / mma.sync (base sm_80+ ISA, OK on compute_103) ----
__device__ __forceinline__ void ldm_x4(uint32_t* r, uint32_t addr) {
    asm volatile("ldmatrix.sync.aligned.m8n8.x4.shared.b16 {%0,%1,%2,%3}, [%4];"
        : "=r"(r[0]), "=r"(r[1]), "=r"(r[2]), "=r"(r[3]) : "r"(addr));
}
__device__ __forceinline__ void mma_bf16(float* d, const uint32_t* a, uint32_t b0, uint32_t b1) {
    asm volatile("mma.sync.aligned.m16n8k16.row.col.f32.bf16.bf16.f32 "
        "{%0,%1,%2,%3}, {%4,%5,%6,%7}, {%8,%9}, {%0,%1,%2,%3};"
        : "+f"(d[0]), "+f"(d[1]), "+f"(d[2]), "+f"(d[3])
        : "r"(a[0]), "r"(a[1]), "r"(a[2]), "r"(a[3]), "r"(b0), "r"(b1));
}

// =====================================================================
// fp32 -> bf16 hi/lo split (vectorized x4)
// =====================================================================
__global__ void cvt_hilo_kernel(const float* __restrict__ s,
                                __nv_bfloat16* __restrict__ hi,
                                __nv_bfloat16* __restrict__ lo, int n4)
{
    int i = blockIdx.x * 256 + threadIdx.x;
    if (i >= n4) return;
    float4 v = ((const float4*)s)[i];
    __nv_bfloat16 h0 = __float2bfloat16(v.x), h1 = __float2bfloat16(v.y);
    __nv_bfloat16 h2 = __float2bfloat16(v.z), h3 = __float2bfloat16(v.w);
    __nv_bfloat162* hp = (__nv_bfloat162*)hi;
    hp[i * 2]     = __nv_bfloat162{h0, h1};
    hp[i * 2 + 1] = __nv_bfloat162{h2, h3};
    __nv_bfloat162* lp = (__nv_bfloat162*)lo;
    lp[i * 2]     = __nv_bfloat162{__float2bfloat16(v.x - __bfloat162float(h0)),
                                   __float2bfloat16(v.y - __bfloat162float(h1))};
    lp[i * 2 + 1] = __nv_bfloat162{__float2bfloat16(v.z - __bfloat162float(h2)),
                                   __float2bfloat16(v.w - __bfloat162float(h3))};
}

// =====================================================================
// bf16x3 GEMM via mma.sync.m16n8k16:
// gx[dir][m][n] = sum_k A[m][k]*W[n][k] + bih[n] + bhh[n]
// passes: Ahi*Whi + Alo*Whi + Ahi*Wlo.
// CTA tile 128x128, K-chunk 64 in smem, 8 warps (2m x 4n), warp tile 64x32.
// grid: (4 nblk, 512 mblk, 2 dir)
// =====================================================================
#define KC   64
#define AROW 72   // KC + 8 pad (bf16 elems); 144B row stride

__global__ __launch_bounds__(256, 2)
void gemm_mma_kernel(const __nv_bfloat16* __restrict__ xhi,
                     const __nv_bfloat16* __restrict__ xlo,
                     const __nv_bfloat16* __restrict__ whi,
                     const __nv_bfloat16* __restrict__ wlo,
                     const float* __restrict__ bihf, const float* __restrict__ bhhf,
                     const float* __restrict__ bihb, const float* __restrict__ bhhb,
                     float* __restrict__ gx)
{
    __shared__ float sbias[128];
    __shared__ __nv_bfloat16 sA[128 * AROW];
    __shared__ __nv_bfloat16 sB[128 * AROW];

    const int tid = threadIdx.x;
    const int lane = tid & 31;
    const int wid = tid >> 5;
    const int warp_m = wid >> 2;   // 0..1
    const int warp_n = wid & 3;    // 0..3
    const int m0 = blockIdx.y * 128;
    const int n0 = blockIdx.x * 128;
    const int dir = blockIdx.z;
    const __nv_bfloat16* Wh = whi + (size_t)dir * G4 * DD;
    const __nv_bfloat16* Wl = wlo + (size_t)dir * G4 * DD;
    const float* bih = dir ? bihb : bihf;
    const float* bhh = dir ? bhhb : bhhf;

    if (tid < 128) sbias[tid] = bih[n0 + tid] + bhh[n0 + tid];

    float acc[4][4][4];
#pragma unroll
    for (int mt = 0; mt < 4; mt++)
#pragma unroll
        for (int nt = 0; nt < 4; nt++)
#pragma unroll
            for (int q = 0; q < 4; q++) acc[mt][nt][q] = 0.0f;

    // precomputed ldmatrix smem addresses (constant across chunks)
    // A: rows of this warp's 16-row tiles; lanes 0-15 rows, 16-31 rows +16B col
    uint32_t aAddr[4], bAddr[2];
#pragma unroll
    for (int mt = 0; mt < 4; mt++) {
        int row = warp_m * 64 + mt * 16 + (lane & 15);
        aAddr[mt] = smem_u32(&sA[row * AROW + (lane >> 4) * 8]);
    }
#pragma unroll
    for (int nh = 0; nh < 2; nh++) {
        int row = warp_n * 32 + nh * 16 + (lane & 15);
        bAddr[nh] = smem_u32(&sB[row * AROW + (lane >> 4) * 8]);
    }

    for (int pass = 0; pass < 3; pass++) {
        const __nv_bfloat16* Asrc = (pass == 1) ? xlo : xhi;
        const __nv_bfloat16* Bsrc = (pass == 2) ? Wl : Wh;
        for (int kc = 0; kc < DD; kc += KC) {
            __syncthreads();
#pragma unroll
            for (int i = 0; i < 4; i++) {
                int u = tid + i * 256;     // 0..1023
                int row = u >> 3;          // 0..127
                int c8 = (u & 7) * 8;      // 0..56
                *(uint4*)&sA[row * AROW + c8] =
                    *(const uint4*)(Asrc + (size_t)(m0 + row) * DD + kc + c8);
                *(uint4*)&sB[row * AROW + c8] =
                    *(const uint4*)(Bsrc + (size_t)(n0 + row) * DD + kc + c8);
            }
            __syncthreads();

#pragma unroll
            for (int k16 = 0; k16 < KC / 16; k16++) {
                uint32_t a[4][4], b[2][4];
#pragma unroll
                for (int mt = 0; mt < 4; mt++)
                    ldm_x4(a[mt], aAddr[mt] + k16 * 32);
#pragma unroll
                for (int nh = 0; nh < 2; nh++)
                    ldm_x4(b[nh], bAddr[nh] + k16 * 32);
#pragma unroll
                for (int mt = 0; mt < 4; mt++)
#pragma unroll
                    for (int nt = 0; nt < 4; nt++) {
                        int nh = nt >> 1, sub = nt & 1;
                        mma_bf16(acc[mt][nt], a[mt], b[nh][sub], b[nh][sub + 2]);
                    }
            }
        }
    }

    // epilogue
    float* gxd = gx + (size_t)dir * M_TOTAL * G4;
#pragma unroll
    for (int mt = 0; mt < 4; mt++) {
        int r0 = m0 + warp_m * 64 + mt * 16 + (lane >> 2);
#pragma unroll
        for (int nt = 0; nt < 4; nt++) {
            int cidx = warp_n * 32 + nt * 8 + (lane & 3) * 2;
            int col = n0 + cidx;
            float2 v0 = make_float2(acc[mt][nt][0] + sbias[cidx],
                                    acc[mt][nt][1] + sbias[cidx + 1]);
            float2 v1 = make_float2(acc[mt][nt][2] + sbias[cidx],
                                    acc[mt][nt][3] + sbias[cidx + 1]);
            *(float2*)(gxd + (size_t)r0 * G4 + col) = v0;
            *(float2*)(gxd + (size_t)(r0 + 8) * G4 + col) = v1;
        }
    }
}

// =====================================================================
// LSTM scan: one block per (dir,batch), 256 threads, 2 gate rows per
// thread (j, j+256) sharing the broadcast h loads. W_hh: 96 cols in
// regs per row, 32 in smem.
// =====================================================================
#define KREG 96
#define KS   32
#define NK4  (KS / 4)  // 8
#define SCAN_SMEM (NK4 * 2 * 256 * 16 + (HH + G4) * 4)  // 65536 + 2560

__global__ __launch_bounds__(256, 1)
void lstm_scan_kernel(const float* __restrict__ gx,
                      const float* __restrict__ w_hh_f,
                      const float* __restrict__ w_hh_b,
                      float* __restrict__ outseq)
{
    float* smem = (float*)smem_raw;
    const int bid = blockIdx.x;     // 0..127
    const int dir = bid >> 6;
    const int b   = bid & 63;
    const int j   = threadIdx.x;    // 0..255, rows j and j+256
    const float* W = dir ? w_hh_b : w_hh_f;

    ulonglong2* ws2 = (ulonglong2*)smem;            // [NK4][2][256]
    float* sh = smem + NK4 * 2 * 256 * 4;           // h[128]
    float* sg = sh + HH;                            // gates[512]

    u64 wr0[KREG / 2], wr1[KREG / 2];
    {
        const u64* wp0 = (const u64*)(W + (size_t)j * HH);
        const u64* wp1 = (const u64*)(W + (size_t)(j + 256) * HH);
#pragma unroll
        for (int p = 0; p < KREG / 2; p++) { wr0[p] = wp0[p]; wr1[p] = wp1[p]; }
    }
#pragma unroll
    for (int k4 = 0; k4 < NK4; k4++) {
        ws2[(k4 * 2 + 0) * 256 + j] = *(const ulonglong2*)(W + (size_t)j * HH + KREG + k4 * 4);
        ws2[(k4 * 2 + 1) * 256 + j] = *(const ulonglong2*)(W + (size_t)(j + 256) * HH + KREG + k4 * 4);
    }
    if (j < HH) sh[j] = 0.0f;
    float c = 0.0f;
    __syncthreads();

    const float* gxb = gx + ((size_t)dir * BB + b) * TT * G4;
    const int dt = dir ? -1 : 1;
    int tt = dir ? (TT - 1) : 0;
    float g0 = gxb[(size_t)tt * G4 + j];
    float g1 = gxb[(size_t)tt * G4 + j + 256];

    for (int t = 0; t < TT; t++) {
        int ttn = tt + dt;
        float gn0 = 0.f, gn1 = 0.f;
        if (t < TT - 1) {
            gn0 = gxb[(size_t)ttn * G4 + j];
            gn1 = gxb[(size_t)ttn * G4 + j + 256];
        }

        u64 a0a = 0ull, a0b = 0ull, a1a = 0ull, a1b = 0ull;
#pragma unroll
        for (int p = 0; p < KREG / 2; p += 2) {
            ulonglong2 h2 = *(const ulonglong2*)(sh + p * 2);   // h[2p..2p+3]
            fma2(a0a, wr0[p],     h2.x);
            fma2(a0b, wr0[p + 1], h2.y);
            fma2(a1a, wr1[p],     h2.x);
            fma2(a1b, wr1[p + 1], h2.y);
        }
#pragma unroll
        for (int k4 = 0; k4 < NK4; k4++) {
            ulonglong2 h2 = *(const ulonglong2*)(sh + KREG + k4 * 4);
            ulonglong2 w0 = ws2[(k4 * 2 + 0) * 256 + j];
            fma2(a0a, w0.x, h2.x);
            fma2(a0b, w0.y, h2.y);
            ulonglong2 w1 = ws2[(k4 * 2 + 1) * 256 + j];
            fma2(a1a, w1.x, h2.x);
            fma2(a1b, w1.y, h2.y);
        }
        u64 s0, s1;
        add2(s0, a0a, a0b);
        add2(s1, a1a, a1b);
        float2 v0 = unpk(s0), v1 = unpk(s1);
        sg[j]       = g0 + v0.x + v0.y;
        sg[j + 256] = g1 + v1.x + v1.y;
        __syncthreads();

        if (j < HH) {
            float ig = sigf(sg[j]);
            float fg = sigf(sg[j + 128]);
            float gg = tanhf(sg[j + 256]);
            float og = sigf(sg[j + 384]);
            c = fg * c + ig * gg;
            float h = og * tanhf(c);
            sh[j] = h;
            outseq[((size_t)b * TT + tt) * (2 * HH) + dir * HH + j] = h;
        }
        __syncthreads();

        g0 = gn0; g1 = gn1;
        tt = ttn;
    }
}

// =====================================================================
// Emissions: one warp per row.
// =====================================================================
__global__ void emissions_kernel(const float* __restrict__ seq,
                                 const float* __restrict__ fcw,
                                 const float* __restrict__ fcb,
                                 float* __restrict__ em)
{
    int gw = (int)((blockIdx.x * blockDim.x + threadIdx.x) >> 5);
    int lane = threadIdx.x & 31;
    if (gw >= M_TOTAL) return;
    const float* row = seq + (size_t)gw * 256 + lane * 8;
    float4 xa = *(const float4*)(row);
    float4 xb = *(const float4*)(row + 4);
#pragma unroll
    for (int tag = 0; tag < NTAGS; tag++) {
        const float* w = fcw + tag * 256 + lane * 8;
        float4 wa = *(const float4*)(w);
        float4 wb = *(const float4*)(w + 4);
        float p = xa.x * wa.x + xa.y * wa.y + xa.z * wa.z + xa.w * wa.w
                + xb.x * wb.x + xb.y * wb.y + xb.z * wb.z + xb.w * wb.w;
#pragma unroll
        for (int off = 16; off > 0; off >>= 1)
            p += __shfl_xor_sync(0xffffffffu, p, off);
        if (lane == 0) em[(size_t)gw * NTAGS + tag] = p + fcb[tag];
    }
}

// =====================================================================
// CRF
// =====================================================================
__global__ void crf_batch_kernel(const float* __restrict__ em,
                                 const int* __restrict__ tags,
                                 const float* __restrict__ startv,
                                 const float* __restrict__ endv,
                                 const float* __restrict__ trans,
                                 float* __restrict__ part)
{
    int b = blockIdx.x;
    int lane = threadIdx.x;
    const float* emb = em + (size_t)b * TT * NTAGS;
    const int* tg = tags + (size_t)b * TT;

    float s = 0.0f;
    for (int t = lane; t < TT; t += 32) {
        int tag = tg[t];
        s += emb[t * NTAGS + tag];
        if (t > 0) s += trans[tg[t - 1] * NTAGS + tag];
    }
#pragma unroll
    for (int off = 16; off > 0; off >>= 1)
        s += __shfl_xor_sync(0xffffffffu, s, off);

    float alpha = -1e30f;
    float tr0 = 0.f, tr1 = 0.f, tr2 = 0.f;
    if (lane < NTAGS) {
        alpha = startv[lane] + emb[lane];
        tr0 = trans[0 * NTAGS + lane];
        tr1 = trans[1 * NTAGS + lane];
        tr2 = trans[2 * NTAGS + lane];
    }
    for (int t = 1; t < TT; t++) {
        float a0 = __shfl_sync(0xffffffffu, alpha, 0);
        float a1 = __shfl_sync(0xffffffffu, alpha, 1);
        float a2 = __shfl_sync(0xffffffffu, alpha, 2);
        if (lane < NTAGS) {
            float v0 = a0 + tr0, v1 = a1 + tr1, v2 = a2 + tr2;
            float m = fmaxf(v0, fmaxf(v1, v2));
            alpha = emb[t * NTAGS + lane] + m +
                    logf(expf(v0 - m) + expf(v1 - m) + expf(v2 - m));
        }
    }
    if (lane < NTAGS) alpha += endv[lane];
    float a0 = __shfl_sync(0xffffffffu, alpha, 0);
    float a1 = __shfl_sync(0xffffffffu, alpha, 1);
    float a2 = __shfl_sync(0xffffffffu, alpha, 2);
    if (lane == 0) {
        float m = fmaxf(a0, fmaxf(a1, a2));
        float logZ = m + logf(expf(a0 - m) + expf(a1 - m) + expf(a2 - m));
        float num = s + startv[tg[0]] + endv[tg[TT - 1]];
        part[b] = num - logZ;
    }
}

__global__ void crf_reduce_kernel(const float* __restrict__ part, float* __restrict__ out)
{
    float s = 0.0f;
    for (int i = 0; i < BB; i++) s += part[i];
    out[0] = -s / (float)BB;
}

// =====================================================================
extern "C" void kernel_launch(void* const* d_in, const int* in_sizes, int n_in,
                              void* d_out, int out_size)
{
    const float* x         = (const float*)d_in[0];
    const int*   tags      = (const int*)  d_in[1];
    const float* w_ih_l0   = (const float*)d_in[2];
    const float* w_hh_l0   = (const float*)d_in[3];
    const float* b_ih_l0   = (const float*)d_in[4];
    const float* b_hh_l0   = (const float*)d_in[5];
    const float* w_ih_l0r  = (const float*)d_in[6];
    const float* w_hh_l0r  = (const float*)d_in[7];
    const float* b_ih_l0r  = (const float*)d_in[8];
    const float* b_hh_l0r  = (const float*)d_in[9];
    const float* w_ih_l1   = (const float*)d_in[10];
    const float* w_hh_l1   = (const float*)d_in[11];
    const float* b_ih_l1   = (const float*)d_in[12];
    const float* b_hh_l1   = (const float*)d_in[13];
    const float* w_ih_l1r  = (const float*)d_in[14];
    const float* w_hh_l1r  = (const float*)d_in[15];
    const float* b_ih_l1r  = (const float*)d_in[16];
    const float* b_hh_l1r  = (const float*)d_in[17];
    const float* fc_w      = (const float*)d_in[18];
    const float* fc_b      = (const float*)d_in[19];
    const float* crf_start = (const float*)d_in[20];
    const float* crf_end   = (const float*)d_in[21];
    const float* crf_trans = (const float*)d_in[22];

    float* out = (float*)d_out;

    float *gx, *seq0, *seq1, *part;
    __nv_bfloat16 *xhi, *xlo, *whi, *wlo;
    cudaGetSymbolAddress((void**)&gx,   g_gx);
    cudaGetSymbolAddress((void**)&seq0, g_seq0);
    cudaGetSymbolAddress((void**)&seq1, g_seq1);
    cudaGetSymbolAddress((void**)&part, g_part);
    cudaGetSymbolAddress((void**)&xhi,  g_xhi);
    cudaGetSymbolAddress((void**)&xlo,  g_xlo);
    cudaGetSymbolAddress((void**)&whi,  g_whi);
    cudaGetSymbolAddress((void**)&wlo,  g_wlo);

    cudaFuncSetAttribute(lstm_scan_kernel,
                         cudaFuncAttributeMaxDynamicSharedMemorySize, SCAN_SMEM);

    const int NX4 = M_TOTAL * DD / 4;   // x / seq0 elements /4
    const int NW4 = G4 * DD / 4;        // one W_ih /4
    dim3 ggrid(4, 512, 2);

    // ---- layer 0 ----
    cvt_hilo_kernel<<<(NX4 + 255) / 256, 256>>>(x, xhi, xlo, NX4);
    cvt_hilo_kernel<<<(NW4 + 255) / 256, 256>>>(w_ih_l0,  whi,            wlo,            NW4);
    cvt_hilo_kernel<<<(NW4 + 255) / 256, 256>>>(w_ih_l0r, whi + G4 * DD,  wlo + G4 * DD,  NW4);
    gemm_mma_kernel<<<ggrid, 256>>>(xhi, xlo, whi, wlo,
                                    b_ih_l0, b_hh_l0, b_ih_l0r, b_hh_l0r, gx);
    lstm_scan_kernel<<<128, 256, SCAN_SMEM>>>(gx, w_hh_l0, w_hh_l0r, seq0);

    // ---- layer 1 ----
    cvt_hilo_kernel<<<(NX4 + 255) / 256, 256>>>(seq0, xhi, xlo, NX4);
    cvt_hilo_kernel<<<(NW4 + 255) / 256, 256>>>(w_ih_l1,  whi,            wlo,            NW4);
    cvt_hilo_kernel<<<(NW4 + 255) / 256, 256>>>(w_ih_l1r, whi + G4 * DD,  wlo + G4 * DD,  NW4);
    gemm_mma_kernel<<<ggrid, 256>>>(xhi, xlo, whi, wlo,
                                    b_ih_l1, b_hh_l1, b_ih_l1r, b_hh_l1r, gx);
    lstm_scan_kernel<<<128, 256, SCAN_SMEM>>>(gx, w_hh_l1, w_hh_l1r, seq1);

    // ---- emissions + CRF ----
    emissions_kernel<<<(M_TOTAL * 32 + 255) / 256, 256>>>(seq1, fc_w, fc_b, out + 1);
    crf_batch_kernel<<<BB, 32>>>(out + 1, tags, crf_start, crf_end, crf_trans, part);
    crf_reduce_kernel<<<1, 1>>>(part, out);
}

// round 6
// speedup vs baseline: 1.7730x; 1.0314x over previous
#include <cuda_runtime.h>
#include <cuda_bf16.h>
#include <math.h>
#include <cstdint>

#define BB 64
#define TT 1024
#define DD 256
#define HH 128
#define G4 512           // 4*H gate width
#define NTAGS 3
#define M_TOTAL (BB*TT)  // 65536

typedef unsigned long long u64;

// single dynamic-shared extern for all kernels
extern __shared__ char smem_raw[];

// ---------------- static scratch (no allocs allowed) ----------------
__device__ float g_gx[(size_t)2 * BB * TT * G4];        // [dir][b][t][512]
__device__ float g_seq0[(size_t)BB * TT * 2 * HH];      // layer0 output
__device__ float g_seq1[(size_t)BB * TT * 2 * HH];      // layer1 output
__device__ float g_part[BB];
__device__ __nv_bfloat16 g_xhi[(size_t)M_TOTAL * DD];   // A hi
__device__ __nv_bfloat16 g_xlo[(size_t)M_TOTAL * DD];   // A lo
__device__ __nv_bfloat16 g_whi[(size_t)2 * G4 * DD];    // W hi (2 dirs)
__device__ __nv_bfloat16 g_wlo[(size_t)2 * G4 * DD];    // W lo

// fast sigmoid / tanh (err ~2^-20, fine vs 1e-3 gate)
__device__ __forceinline__ float fsig(float x) {
    return __fdividef(1.0f, 1.0f + __expf(-x));
}
__device__ __forceinline__ float ftanh_id(float x) {   // 2*sig(2x)-1
    return fmaf(2.0f, __fdividef(1.0f, 1.0f + __expf(-2.0f * x)), -1.0f);
}
// accurate versions for CRF (tiny cost)
__device__ __forceinline__ float sigf(float x) { return 1.0f / (1.0f + expf(-x)); }

// ---- packed f32x2 helpers ----
__device__ __forceinline__ void fma2(u64& d, u64 a, u64 b) {
    asm("fma.rn.f32x2 %0, %1, %2, %0;" : "+l"(d) : "l"(a), "l"(b));
}
__device__ __forceinline__ void add2(u64& d, u64 a, u64 b) {
    asm("add.rn.f32x2 %0, %1, %2;" : "=l"(d) : "l"(a), "l"(b));
}
__device__ __forceinline__ float2 unpk(u64 v) {
    float2 f; asm("mov.b64 {%0, %1}, %2;" : "=f"(f.x), "=f"(f.y) : "l"(v)); return f;
}

__device__ __forceinline__ uint32_t smem_u32(const void* p) {
    uint32_t a;
    asm("{ .reg .u64 t; cvta.to.shared.u64 t, %1; cvt.u32.u64 %0, t; }" : "=r"(a) : "l"(p));
    return a;
}

// ---- ldmatrix / mma.sync / cp.async (base sm_80+ ISA) ----
__device__ __forceinline__ void ldm_x4(uint32_t* r, uint32_t addr) {
    asm volatile("ldmatrix.sync.aligned.m8n8.x4.shared.b16 {%0,%1,%2,%3}, [%4];"
        : "=r"(r[0]), "=r"(r[1]), "=r"(r[2]), "=r"(r[3]) : "r"(addr));
}
__device__ __forceinline__ void mma_bf16(float* d, const uint32_t* a, uint32_t b0, uint32_t b1) {
    asm volatile("mma.sync.aligned.m16n8k16.row.col.f32.bf16.bf16.f32 "
        "{%0,%1,%2,%3}, {%4,%5,%6,%7}, {%8,%9}, {%0,%1,%2,%3};"
        : "+f"(d[0]), "+f"(d[1]), "+f"(d[2]), "+f"(d[3])
        : "r"(a[0]), "r"(a[1]), "r"(a[2]), "r"(a[3]), "r"(b0), "r"(b1));
}
__device__ __forceinline__ void cpa16(uint32_t dst, const void* src) {
    asm volatile("cp.async.cg.shared.global [%0], [%1], 16;" :: "r"(dst), "l"(src));
}

// =====================================================================
// fp32 -> bf16 hi/lo split (vectorized x4)
// =====================================================================
__global__ void cvt_hilo_kernel(const float* __restrict__ s,
                                __nv_bfloat16* __restrict__ hi,
                                __nv_bfloat16* __restrict__ lo, int n4)
{
    int i = blockIdx.x * 256 + threadIdx.x;
    if (i >= n4) return;
    float4 v = ((const float4*)s)[i];
    __nv_bfloat16 h0 = __float2bfloat16(v.x), h1 = __float2bfloat16(v.y);
    __nv_bfloat16 h2 = __float2bfloat16(v.z), h3 = __float2bfloat16(v.w);
    __nv_bfloat162* hp = (__nv_bfloat162*)hi;
    hp[i * 2]     = __nv_bfloat162{h0, h1};
    hp[i * 2 + 1] = __nv_bfloat162{h2, h3};
    __nv_bfloat162* lp = (__nv_bfloat162*)lo;
    lp[i * 2]     = __nv_bfloat162{__float2bfloat16(v.x - __bfloat162float(h0)),
                                   __float2bfloat16(v.y - __bfloat162float(h1))};
    lp[i * 2 + 1] = __nv_bfloat162{__float2bfloat16(v.z - __bfloat162float(h2)),
                                   __float2bfloat16(v.w - __bfloat162float(h3))};
}

// =====================================================================
// bf16x3 GEMM via mma.sync m16n8k16 + 2-stage cp.async pipeline.
// gx[dir][m][n] = sum_k A[m][k]*W[n][k] + bih[n] + bhh[n]
// 12 K-chunks of 64: passes Ahi*Whi (4), Alo*Whi (4), Ahi*Wlo (4).
// CTA tile 128x128, 8 warps (2m x 4n), warp tile 64x32.
// =====================================================================
#define KC    64
#define AROW  72                 // KC + 8 pad (bf16 elems)
#define TILEB (128 * AROW * 2)   // 18432 bytes per matrix tile
#define STAGEB (2 * TILEB)       // 36864 per stage (A + B)
#define GEMM_SMEM (2 * STAGEB)   // 73728

__global__ __launch_bounds__(256, 2)
void gemm_mma_kernel(const __nv_bfloat16* __restrict__ xhi,
                     const __nv_bfloat16* __restrict__ xlo,
                     const __nv_bfloat16* __restrict__ whi,
                     const __nv_bfloat16* __restrict__ wlo,
                     const float* __restrict__ bihf, const float* __restrict__ bhhf,
                     const float* __restrict__ bihb, const float* __restrict__ bhhb,
                     float* __restrict__ gx)
{
    __shared__ float sbias[128];

    const int tid = threadIdx.x;
    const int lane = tid & 31;
    const int wid = tid >> 5;
    const int warp_m = wid >> 2;   // 0..1
    const int warp_n = wid & 3;    // 0..3
    const int m0 = blockIdx.y * 128;
    const int n0 = blockIdx.x * 128;
    const int dir = blockIdx.z;
    const __nv_bfloat16* Wh = whi + (size_t)dir * G4 * DD;
    const __nv_bfloat16* Wl = wlo + (size_t)dir * G4 * DD;
    const float* bih = dir ? bihb : bihf;
    const float* bhh = dir ? bhhb : bhhf;
    const uint32_t sdyn = smem_u32(smem_raw);

    if (tid < 128) sbias[tid] = bih[n0 + tid] + bhh[n0 + tid];

    float acc[4][4][4];
#pragma unroll
    for (int mt = 0; mt < 4; mt++)
#pragma unroll
        for (int nt = 0; nt < 4; nt++)
#pragma unroll
            for (int q = 0; q < 4; q++) acc[mt][nt][q] = 0.0f;

    // ldmatrix byte offsets within a stage
    uint32_t aOff[4], bOff[2];
#pragma unroll
    for (int mt = 0; mt < 4; mt++) {
        int row = warp_m * 64 + mt * 16 + (lane & 15);
        aOff[mt] = (uint32_t)((row * AROW + (lane >> 4) * 8) * 2);
    }
#pragma unroll
    for (int nh = 0; nh < 2; nh++) {
        int row = warp_n * 32 + nh * 16 + (lane & 15);
        bOff[nh] = (uint32_t)(TILEB + (row * AROW + (lane >> 4) * 8) * 2);
    }

    auto prefetch = [&](int c, int st) {
        const __nv_bfloat16* Asrc = (c >= 4 && c < 8) ? xlo : xhi;
        const __nv_bfloat16* Bsrc = (c >= 8) ? Wl : Wh;
        int kc = (c & 3) * KC;
        uint32_t base = sdyn + st * STAGEB;
#pragma unroll
        for (int i = 0; i < 4; i++) {
            int u = tid + i * 256;     // 0..1023
            int row = u >> 3;          // 0..127
            int c8 = (u & 7) * 8;      // 0..56
            cpa16(base + (uint32_t)((row * AROW + c8) * 2),
                  Asrc + (size_t)(m0 + row) * DD + kc + c8);
            cpa16(base + (uint32_t)(TILEB + (row * AROW + c8) * 2),
                  Bsrc + (size_t)(n0 + row) * DD + kc + c8);
        }
        asm volatile("cp.async.commit_group;" ::: "memory");
    };

    prefetch(0, 0);
    for (int c = 0; c < 12; c++) {
        if (c + 1 < 12) {
            prefetch(c + 1, (c + 1) & 1);
            asm volatile("cp.async.wait_group 1;" ::: "memory");
        } else {
            asm volatile("cp.async.wait_group 0;" ::: "memory");
        }
        __syncthreads();

        uint32_t st = sdyn + (uint32_t)((c & 1) * STAGEB);
#pragma unroll
        for (int k16 = 0; k16 < KC / 16; k16++) {
            uint32_t a[4][4], b[2][4];
#pragma unroll
            for (int mt = 0; mt < 4; mt++)
                ldm_x4(a[mt], st + aOff[mt] + k16 * 32);
#pragma unroll
            for (int nh = 0; nh < 2; nh++)
                ldm_x4(b[nh], st + bOff[nh] + k16 * 32);
#pragma unroll
            for (int mt = 0; mt < 4; mt++)
#pragma unroll
                for (int nt = 0; nt < 4; nt++) {
                    int nh = nt >> 1, sub = nt & 1;
                    mma_bf16(acc[mt][nt], a[mt], b[nh][sub], b[nh][sub + 2]);
                }
        }
        __syncthreads();
    }

    // epilogue
    float* gxd = gx + (size_t)dir * M_TOTAL * G4;
#pragma unroll
    for (int mt = 0; mt < 4; mt++) {
        int r0 = m0 + warp_m * 64 + mt * 16 + (lane >> 2);
#pragma unroll
        for (int nt = 0; nt < 4; nt++) {
            int cidx = warp_n * 32 + nt * 8 + (lane & 3) * 2;
            int col = n0 + cidx;
            float2 v0 = make_float2(acc[mt][nt][0] + sbias[cidx],
                                    acc[mt][nt][1] + sbias[cidx + 1]);
            float2 v1 = make_float2(acc[mt][nt][2] + sbias[cidx],
                                    acc[mt][nt][3] + sbias[cidx + 1]);
            *(float2*)(gxd + (size_t)r0 * G4 + col) = v0;
            *(float2*)(gxd + (size_t)(r0 + 8) * G4 + col) = v1;
        }
    }
}

// =====================================================================
// LSTM scan, pair-thread version: one block per (dir,batch), 256 thr.
// Threads (2j, 2j+1) own unit j: even thread -> gate rows j (i) and
// j+256 (g); odd -> j+128 (f) and j+384 (o). Each thread applies its
// own nonlinearity; pair exchanges via shfl_xor(1); even updates c,h.
// h double-buffered in smem -> ONE __syncthreads per step.
// W_hh: 96 K-cols in regs per row, 32 in smem.
// =====================================================================
#define KREG 96
#define KS   32
#define NK4  (KS / 4)  // 8
#define SCAN_SMEM (NK4 * 2 * 256 * 16 + 2 * HH * 4)  // 65536 + 1024

__global__ __launch_bounds__(256, 1)
void lstm_scan_kernel(const float* __restrict__ gx,
                      const float* __restrict__ w_hh_f,
                      const float* __restrict__ w_hh_b,
                      float* __restrict__ outseq)
{
    float* smem = (float*)smem_raw;
    const int bid = blockIdx.x;     // 0..127
    const int dir = bid >> 6;
    const int b   = bid & 63;
    const int j   = threadIdx.x;    // 0..255
    const int odd = j & 1;
    const int unit = j >> 1;        // 0..127
    const int row0 = unit + (odd << 7);   // i or f
    const int row1 = row0 + 256;          // g or o
    const float* W = dir ? w_hh_b : w_hh_f;

    ulonglong2* ws2 = (ulonglong2*)smem;            // [NK4][2][256]
    float* shb = smem + NK4 * 2 * 256 * 4;          // h double buffer [2][128]

    u64 wr0[KREG / 2], wr1[KREG / 2];
    {
        const u64* wp0 = (const u64*)(W + (size_t)row0 * HH);
        const u64* wp1 = (const u64*)(W + (size_t)row1 * HH);
#pragma unroll
        for (int p = 0; p < KREG / 2; p++) { wr0[p] = wp0[p]; wr1[p] = wp1[p]; }
    }
#pragma unroll
    for (int k4 = 0; k4 < NK4; k4++) {
        ws2[(k4 * 2 + 0) * 256 + j] = *(const ulonglong2*)(W + (size_t)row0 * HH + KREG + k4 * 4);
        ws2[(k4 * 2 + 1) * 256 + j] = *(const ulonglong2*)(W + (size_t)row1 * HH + KREG + k4 * 4);
    }
    if (j < HH) shb[j] = 0.0f;      // h_{-1} = 0 in buffer 0
    float c = 0.0f;
    __syncthreads();

    const float* gxb = gx + ((size_t)dir * BB + b) * TT * G4;
    const int dt = dir ? -1 : 1;
    int tt = dir ? (TT - 1) : 0;
    float g0 = gxb[(size_t)tt * G4 + row0];
    float g1 = gxb[(size_t)tt * G4 + row1];

    for (int t = 0; t < TT; t++) {
        int ttn = tt + dt;
        float gn0 = 0.f, gn1 = 0.f;
        if (t < TT - 1) {
            gn0 = gxb[(size_t)ttn * G4 + row0];
            gn1 = gxb[(size_t)ttn * G4 + row1];
        }

        const float* sh = shb + ((t & 1) << 7);        // read h_{t-1}
        float* shw = shb + (((t + 1) & 1) << 7);       // write h_t

        u64 a0a = 0ull, a0b = 0ull, a1a = 0ull, a1b = 0ull;
#pragma unroll
        for (int p = 0; p < KREG / 2; p += 2) {
            ulonglong2 h2 = *(const ulonglong2*)(sh + p * 2);   // h[2p..2p+3]
            fma2(a0a, wr0[p],     h2.x);
            fma2(a0b, wr0[p + 1], h2.y);
            fma2(a1a, wr1[p],     h2.x);
            fma2(a1b, wr1[p + 1], h2.y);
        }
#pragma unroll
        for (int k4 = 0; k4 < NK4; k4++) {
            ulonglong2 h2 = *(const ulonglong2*)(sh + KREG + k4 * 4);
            ulonglong2 w0 = ws2[(k4 * 2 + 0) * 256 + j];
            fma2(a0a, w0.x, h2.x);
            fma2(a0b, w0.y, h2.y);
            ulonglong2 w1 = ws2[(k4 * 2 + 1) * 256 + j];
            fma2(a1a, w1.x, h2.x);
            fma2(a1b, w1.y, h2.y);
        }
        u64 s0, s1;
        add2(s0, a0a, a0b);
        add2(s1, a1a, a1b);
        float2 v0 = unpk(s0), v1 = unpk(s1);
        float a0 = g0 + v0.x + v0.y;   // i or f pre-activation
        float a1 = g1 + v1.x + v1.y;   // g or o pre-activation

        // nonlinearity, branch-free: even needs tanh(a1)=2*sig(2*a1)-1
        float p0 = fsig(a0);
        float scale = odd ? 1.0f : 2.0f;
        float s = fsig(a1 * scale);
        float p1 = odd ? s : fmaf(2.0f, s, -1.0f);

        float q0 = __shfl_xor_sync(0xffffffffu, p0, 1);  // even gets f
        float q1 = __shfl_xor_sync(0xffffffffu, p1, 1);  // even gets o

        if (!odd) {
            c = q0 * c + p0 * p1;            // f*c + i*g
            float h = q1 * ftanh_id(c);      // o*tanh(c)
            shw[unit] = h;
            outseq[((size_t)b * TT + tt) * (2 * HH) + dir * HH + unit] = h;
        }
        __syncthreads();

        g0 = gn0; g1 = gn1;
        tt = ttn;
    }
}

// =====================================================================
// Emissions: one warp per row.
// =====================================================================
__global__ void emissions_kernel(const float* __restrict__ seq,
                                 const float* __restrict__ fcw,
                                 const float* __restrict__ fcb,
                                 float* __restrict__ em)
{
    int gw = (int)((blockIdx.x * blockDim.x + threadIdx.x) >> 5);
    int lane = threadIdx.x & 31;
    if (gw >= M_TOTAL) return;
    const float* row = seq + (size_t)gw * 256 + lane * 8;
    float4 xa = *(const float4*)(row);
    float4 xb = *(const float4*)(row + 4);
#pragma unroll
    for (int tag = 0; tag < NTAGS; tag++) {
        const float* w = fcw + tag * 256 + lane * 8;
        float4 wa = *(const float4*)(w);
        float4 wb = *(const float4*)(w + 4);
        float p = xa.x * wa.x + xa.y * wa.y + xa.z * wa.z + xa.w * wa.w
                + xb.x * wb.x + xb.y * wb.y + xb.z * wb.z + xb.w * wb.w;
#pragma unroll
        for (int off = 16; off > 0; off >>= 1)
            p += __shfl_xor_sync(0xffffffffu, p, off);
        if (lane == 0) em[(size_t)gw * NTAGS + tag] = p + fcb[tag];
    }
}

// =====================================================================
// CRF
// =====================================================================
__global__ void crf_batch_kernel(const float* __restrict__ em,
                                 const int* __restrict__ tags,
                                 const float* __restrict__ startv,
                                 const float* __restrict__ endv,
                                 const float* __restrict__ trans,
                                 float* __restrict__ part)
{
    int b = blockIdx.x;
    int lane = threadIdx.x;
    const float* emb = em + (size_t)b * TT * NTAGS;
    const int* tg = tags + (size_t)b * TT;

    float s = 0.0f;
    for (int t = lane; t < TT; t += 32) {
        int tag = tg[t];
        s += emb[t * NTAGS + tag];
        if (t > 0) s += trans[tg[t - 1] * NTAGS + tag];
    }
#pragma unroll
    for (int off = 16; off > 0; off >>= 1)
        s += __shfl_xor_sync(0xffffffffu, s, off);

    float alpha = -1e30f;
    float tr0 = 0.f, tr1 = 0.f, tr2 = 0.f;
    if (lane < NTAGS) {
        alpha = startv[lane] + emb[lane];
        tr0 = trans[0 * NTAGS + lane];
        tr1 = trans[1 * NTAGS + lane];
        tr2 = trans[2 * NTAGS + lane];
    }
    for (int t = 1; t < TT; t++) {
        float a0 = __shfl_sync(0xffffffffu, alpha, 0);
        float a1 = __shfl_sync(0xffffffffu, alpha, 1);
        float a2 = __shfl_sync(0xffffffffu, alpha, 2);
        if (lane < NTAGS) {
            float v0 = a0 + tr0, v1 = a1 + tr1, v2 = a2 + tr2;
            float m = fmaxf(v0, fmaxf(v1, v2));
            alpha = emb[t * NTAGS + lane] + m +
                    logf(expf(v0 - m) + expf(v1 - m) + expf(v2 - m));
        }
    }
    if (lane < NTAGS) alpha += endv[lane];
    float a0 = __shfl_sync(0xffffffffu, alpha, 0);
    float a1 = __shfl_sync(0xffffffffu, alpha, 1);
    float a2 = __shfl_sync(0xffffffffu, alpha, 2);
    if (lane == 0) {
        float m = fmaxf(a0, fmaxf(a1, a2));
        float logZ = m + logf(expf(a0 - m) + expf(a1 - m) + expf(a2 - m));
        float num = s + startv[tg[0]] + endv[tg[TT - 1]];
        part[b] = num - logZ;
    }
}

__global__ void crf_reduce_kernel(const float* __restrict__ part, float* __restrict__ out)
{
    float s = 0.0f;
    for (int i = 0; i < BB; i++) s += part[i];
    out[0] = -s / (float)BB;
}

// =====================================================================
extern "C" void kernel_launch(void* const* d_in, const int* in_sizes, int n_in,
                              void* d_out, int out_size)
{
    const float* x         = (const float*)d_in[0];
    const int*   tags      = (const int*)  d_in[1];
    const float* w_ih_l0   = (const float*)d_in[2];
    const float* w_hh_l0   = (const float*)d_in[3];
    const float* b_ih_l0   = (const float*)d_in[4];
    const float* b_hh_l0   = (const float*)d_in[5];
    const float* w_ih_l0r  = (const float*)d_in[6];
    const float* w_hh_l0r  = (const float*)d_in[7];
    const float* b_ih_l0r  = (const float*)d_in[8];
    const float* b_hh_l0r  = (const float*)d_in[9];
    const float* w_ih_l1   = (const float*)d_in[10];
    const float* w_hh_l1   = (const float*)d_in[11];
    const float* b_ih_l1   = (const float*)d_in[12];
    const float* b_hh_l1   = (const float*)d_in[13];
    const float* w_ih_l1r  = (const float*)d_in[14];
    const float* w_hh_l1r  = (const float*)d_in[15];
    const float* b_ih_l1r  = (const float*)d_in[16];
    const float* b_hh_l1r  = (const float*)d_in[17];
    const float* fc_w      = (const float*)d_in[18];
    const float* fc_b      = (const float*)d_in[19];
    const float* crf_start = (const float*)d_in[20];
    const float* crf_end   = (const float*)d_in[21];
    const float* crf_trans = (const float*)d_in[22];

    float* out = (float*)d_out;

    float *gx, *seq0, *seq1, *part;
    __nv_bfloat16 *xhi, *xlo, *whi, *wlo;
    cudaGetSymbolAddress((void**)&gx,   g_gx);
    cudaGetSymbolAddress((void**)&seq0, g_seq0);
    cudaGetSymbolAddress((void**)&seq1, g_seq1);
    cudaGetSymbolAddress((void**)&part, g_part);
    cudaGetSymbolAddress((void**)&xhi,  g_xhi);
    cudaGetSymbolAddress((void**)&xlo,  g_xlo);
    cudaGetSymbolAddress((void**)&whi,  g_whi);
    cudaGetSymbolAddress((void**)&wlo,  g_wlo);

    cudaFuncSetAttribute(lstm_scan_kernel,
                         cudaFuncAttributeMaxDynamicSharedMemorySize, SCAN_SMEM);
    cudaFuncSetAttribute(gemm_mma_kernel,
                         cudaFuncAttributeMaxDynamicSharedMemorySize, GEMM_SMEM);

    const int NX4 = M_TOTAL * DD / 4;
    const int NW4 = G4 * DD / 4;
    dim3 ggrid(4, 512, 2);

    // ---- layer 0 ----
    cvt_hilo_kernel<<<(NX4 + 255) / 256, 256>>>(x, xhi, xlo, NX4);
    cvt_hilo_kernel<<<(NW4 + 255) / 256, 256>>>(w_ih_l0,  whi,            wlo,            NW4);
    cvt_hilo_kernel<<<(NW4 + 255) / 256, 256>>>(w_ih_l0r, whi + G4 * DD,  wlo + G4 * DD,  NW4);
    gemm_mma_kernel<<<ggrid, 256, GEMM_SMEM>>>(xhi, xlo, whi, wlo,
                                               b_ih_l0, b_hh_l0, b_ih_l0r, b_hh_l0r, gx);
    lstm_scan_kernel<<<128, 256, SCAN_SMEM>>>(gx, w_hh_l0, w_hh_l0r, seq0);

    // ---- layer 1 ----
    cvt_hilo_kernel<<<(NX4 + 255) / 256, 256>>>(seq0, xhi, xlo, NX4);
    cvt_hilo_kernel<<<(NW4 + 255) / 256, 256>>>(w_ih_l1,  whi,            wlo,            NW4);
    cvt_hilo_kernel<<<(NW4 + 255) / 256, 256>>>(w_ih_l1r, whi + G4 * DD,  wlo + G4 * DD,  NW4);
    gemm_mma_kernel<<<ggrid, 256, GEMM_SMEM>>>(xhi, xlo, whi, wlo,
                                               b_ih_l1, b_hh_l1, b_ih_l1r, b_hh_l1r, gx);
    lstm_scan_kernel<<<128, 256, SCAN_SMEM>>>(gx, w_hh_l1, w_hh_l1r, seq1);

    // ---- emissions + CRF ----
    emissions_kernel<<<(M_TOTAL * 32 + 255) / 256, 256>>>(seq1, fc_w, fc_b, out + 1);
    crf_batch_kernel<<<BB, 32>>>(out + 1, tags, crf_start, crf_end, crf_trans, part);
    crf_reduce_kernel<<<1, 1>>>(part, out);
}